// round 3
// baseline (speedup 1.0000x reference)
#include <cuda_runtime.h>
#include <cstdint>
#include <cstddef>

#define BB 2
#define TT 2048
#define DD 1024
#define HH 16
#define HS 64
#define BT (BB*TT)

// Scratch (allocation-free rule: __device__ globals)
__device__ float g_q[BB*HH*TT*HS];
__device__ float g_k[BB*HH*TT*HS];
__device__ float g_v[BB*HH*TT*HS];
__device__ float g_y[BT*DD];

__device__ __forceinline__ uint32_t f2tf(float x){
    uint32_t r; asm("cvt.rna.tf32.f32 %0, %1;" : "=r"(r) : "f"(x)); return r;
}
__device__ __forceinline__ float f2tff(float x){ return __uint_as_float(f2tf(x)); }

__device__ __forceinline__ void mma8(float* c, const uint32_t* a, const uint32_t* b){
    asm volatile(
        "mma.sync.aligned.m16n8k8.row.col.f32.tf32.tf32.f32 "
        "{%0,%1,%2,%3}, {%4,%5,%6,%7}, {%8,%9}, {%0,%1,%2,%3};\n"
        : "+f"(c[0]), "+f"(c[1]), "+f"(c[2]), "+f"(c[3])
        : "r"(a[0]), "r"(a[1]), "r"(a[2]), "r"(a[3]), "r"(b[0]), "r"(b[1]));
}

// ---------------------------------------------------------------------------
// 128x128 tile of A(MxK row-major) * W^T (W is NxK row-major), K = DD = 1024.
// 256 threads, 8 warps; warp tile 64x32 (4 m-frags x 4 n-frags of m16n8).
// ---------------------------------------------------------------------------
__device__ __forceinline__ void gemm_128_128(
    const float* __restrict__ A, const float* __restrict__ W,
    int m0, int n0, float acc[16][4], float* sA, float* sB)
{
    const int t = threadIdx.x, lane = t & 31, warp = t >> 5;
    const int wm = (warp >> 2) * 64, wn = (warp & 3) * 32;
    const int r = lane >> 2, c = lane & 3;
    const int lrow = t >> 3, lc4 = (t & 7) * 4;

    float4 ra[4], rb[4];
    #pragma unroll
    for (int i = 0; i < 4; i++){
        ra[i] = *(const float4*)(A + (size_t)(m0 + lrow + 32*i)*DD + lc4);
        rb[i] = *(const float4*)(W + (size_t)(n0 + lrow + 32*i)*DD + lc4);
    }
    #pragma unroll
    for (int i = 0; i < 16; i++){ acc[i][0]=acc[i][1]=acc[i][2]=acc[i][3]=0.f; }

    for (int k0 = 0; k0 < DD; k0 += 32){
        #pragma unroll
        for (int i = 0; i < 4; i++){
            float4 ca, cb;
            ca.x=f2tff(ra[i].x); ca.y=f2tff(ra[i].y); ca.z=f2tff(ra[i].z); ca.w=f2tff(ra[i].w);
            cb.x=f2tff(rb[i].x); cb.y=f2tff(rb[i].y); cb.z=f2tff(rb[i].z); cb.w=f2tff(rb[i].w);
            *(float4*)(sA + (lrow + 32*i)*36 + lc4) = ca;
            *(float4*)(sB + (lrow + 32*i)*36 + lc4) = cb;
        }
        __syncthreads();
        const bool nxt = (k0 + 32) < DD;
        if (nxt){
            #pragma unroll
            for (int i = 0; i < 4; i++){
                ra[i] = *(const float4*)(A + (size_t)(m0 + lrow + 32*i)*DD + k0 + 32 + lc4);
                rb[i] = *(const float4*)(W + (size_t)(n0 + lrow + 32*i)*DD + k0 + 32 + lc4);
            }
        }
        #pragma unroll
        for (int ks = 0; ks < 4; ks++){
            uint32_t af[4][4], bf[4][2];
            #pragma unroll
            for (int mt = 0; mt < 4; mt++){
                const float* p = sA + (wm + mt*16 + r)*36 + ks*8 + c;
                af[mt][0] = __float_as_uint(p[0]);
                af[mt][1] = __float_as_uint(p[8*36]);
                af[mt][2] = __float_as_uint(p[4]);
                af[mt][3] = __float_as_uint(p[8*36 + 4]);
            }
            #pragma unroll
            for (int nt = 0; nt < 4; nt++){
                const float* p = sB + (wn + nt*8 + r)*36 + ks*8 + c;
                bf[nt][0] = __float_as_uint(p[0]);
                bf[nt][1] = __float_as_uint(p[4]);
            }
            #pragma unroll
            for (int mt = 0; mt < 4; mt++)
                #pragma unroll
                for (int nt = 0; nt < 4; nt++)
                    mma8(acc[mt*4 + nt], af[mt], bf[nt]);
        }
        __syncthreads();
    }
}

// ---------------------------------------------------------------------------
// K1: QKV projection.  grid (32, 8, 3), 256 thr.
// Writes tf32-rounded q/k/v in [B,H,T,HS] layout.
// ---------------------------------------------------------------------------
extern "C" __global__ void __launch_bounds__(256, 1)
qkv_kernel(const float* __restrict__ x, const float* __restrict__ Wq,
           const float* __restrict__ Wk, const float* __restrict__ Wv)
{
    __shared__ float sA[128*36];
    __shared__ float sB[128*36];
    const float* W = (blockIdx.z == 0) ? Wq : ((blockIdx.z == 1) ? Wk : Wv);
    float* dst     = (blockIdx.z == 0) ? g_q : ((blockIdx.z == 1) ? g_k : g_v);
    const int m0 = blockIdx.x * 128, n0 = blockIdx.y * 128;

    float acc[16][4];
    gemm_128_128(x, W, m0, n0, acc, sA, sB);

    const int lane = threadIdx.x & 31, warp = threadIdx.x >> 5;
    const int wm = (warp >> 2) * 64, wn = (warp & 3) * 32;
    const int r = lane >> 2, c = lane & 3;
    #pragma unroll
    for (int mt = 0; mt < 4; mt++){
        #pragma unroll
        for (int nt = 0; nt < 4; nt++){
            const float* f = acc[mt*4 + nt];
            const int m_ = m0 + wm + mt*16 + r;
            const int n_ = n0 + wn + nt*8 + c*2;
            const int b  = m_ >> 11, h = n_ >> 6, hs = n_ & 63;
            const int t0 = m_ & 2047, t1 = (m_ + 8) & 2047;
            float2 v0 = make_float2(f2tff(f[0]), f2tff(f[1]));
            float2 v1 = make_float2(f2tff(f[2]), f2tff(f[3]));
            *(float2*)(dst + ((size_t)((b<<4) + h)*TT + t0)*HS + hs) = v0;
            *(float2*)(dst + ((size_t)((b<<4) + h)*TT + t1)*HS + hs) = v1;
        }
    }
}

// ---------------------------------------------------------------------------
// K2: fused attention.  grid (T/128=16, H=16, B=2), 256 thr, dynamic smem.
// Pass 1: l[q] = sum_k exp(q.k/8) (no max needed: |s| <= ~3.3).
// Pass 2: att = exp(s)/l -> smem P tile -> coalesced gmem store + P*V MMAs.
// ---------------------------------------------------------------------------
extern "C" __global__ void __launch_bounds__(256, 1)
attn_kernel(float* __restrict__ att)
{
    extern __shared__ float sm[];
    float* sQ = sm;                    // 128 x (64 + 4 pad)
    float* sK = sQ + 128*68;           // 128 x (64 + 4 pad)
    float* sV = sK + 128*68;           // 128 x (64 + 8 pad)
    float* sP = sV + 128*72;           // 128 x (128 + 4 pad)
    float* sL = sP + 128*132;          // 128 row sums

    const int t = threadIdx.x, lane = t & 31, warp = t >> 5;
    const int r = lane >> 2, c = lane & 3;
    const int qb = blockIdx.x, h = blockIdx.y, b = blockIdx.z;

    const size_t headoff = (size_t)(b*HH + h) * TT * HS;
    const float* Qg = g_q + headoff + (size_t)qb * 128 * HS;
    const float* Kg = g_k + headoff;
    const float* Vg = g_v + headoff;
    float* attg = att + ((size_t)(b*HH + h)*TT + (size_t)qb*128) * TT;

    // load Q tile
    #pragma unroll
    for (int i = 0; i < 8; i++){
        const int idx = t + 256*i, row = idx >> 4, col = (idx & 15) * 4;
        *(float4*)(sQ + row*68 + col) = *(const float4*)(Qg + row*64 + col);
    }
    __syncthreads();

    // preload Q A-fragments (fixed for whole CTA lifetime)
    uint32_t aq[8][4];
    #pragma unroll
    for (int ks = 0; ks < 8; ks++){
        const float* p = sQ + (warp*16 + r)*68 + ks*8 + c;
        aq[ks][0] = __float_as_uint(p[0]);
        aq[ks][1] = __float_as_uint(p[8*68]);
        aq[ks][2] = __float_as_uint(p[4]);
        aq[ks][3] = __float_as_uint(p[8*68 + 4]);
    }

    const float CF = 0.18033688011112042f;   // log2(e) / sqrt(64)

    // ---- PASS 1: row sums of exp(s) ----
    float l0 = 0.f, l1 = 0.f;
    for (int kb = 0; kb < 16; kb++){
        __syncthreads();
        #pragma unroll
        for (int i = 0; i < 8; i++){
            const int idx = t + 256*i, row = idx >> 4, col = (idx & 15) * 4;
            *(float4*)(sK + row*68 + col) = *(const float4*)(Kg + (size_t)(kb*128 + row)*64 + col);
        }
        __syncthreads();

        float s[16][4];
        #pragma unroll
        for (int i = 0; i < 16; i++){ s[i][0]=s[i][1]=s[i][2]=s[i][3]=0.f; }
        #pragma unroll
        for (int ks = 0; ks < 8; ks++){
            #pragma unroll
            for (int nt = 0; nt < 16; nt++){
                uint32_t bf[2];
                const float* p = sK + (nt*8 + r)*68 + ks*8 + c;
                bf[0] = __float_as_uint(p[0]);
                bf[1] = __float_as_uint(p[4]);
                mma8(s[nt], aq[ks], bf);
            }
        }
        #pragma unroll
        for (int nt = 0; nt < 16; nt++){
            l0 += exp2f(s[nt][0]*CF) + exp2f(s[nt][1]*CF);
            l1 += exp2f(s[nt][2]*CF) + exp2f(s[nt][3]*CF);
        }
    }
    l0 += __shfl_xor_sync(0xffffffffu, l0, 1);
    l0 += __shfl_xor_sync(0xffffffffu, l0, 2);
    l1 += __shfl_xor_sync(0xffffffffu, l1, 1);
    l1 += __shfl_xor_sync(0xffffffffu, l1, 2);
    __syncthreads();
    if (c == 0){ sL[warp*16 + r] = l0; sL[warp*16 + r + 8] = l1; }
    __syncthreads();
    const float inv0 = 1.0f / sL[warp*16 + r];
    const float inv1 = 1.0f / sL[warp*16 + r + 8];

    // ---- PASS 2: att store + P*V ----
    float yv[8][4];
    #pragma unroll
    for (int i = 0; i < 8; i++){ yv[i][0]=yv[i][1]=yv[i][2]=yv[i][3]=0.f; }

    for (int kb = 0; kb < 16; kb++){
        __syncthreads();
        #pragma unroll
        for (int i = 0; i < 8; i++){
            const int idx = t + 256*i, row = idx >> 4, col = (idx & 15) * 4;
            *(float4*)(sK + row*68 + col) = *(const float4*)(Kg + (size_t)(kb*128 + row)*64 + col);
            *(float4*)(sV + row*72 + col) = *(const float4*)(Vg + (size_t)(kb*128 + row)*64 + col);
        }
        __syncthreads();

        float s[16][4];
        #pragma unroll
        for (int i = 0; i < 16; i++){ s[i][0]=s[i][1]=s[i][2]=s[i][3]=0.f; }
        #pragma unroll
        for (int ks = 0; ks < 8; ks++){
            #pragma unroll
            for (int nt = 0; nt < 16; nt++){
                uint32_t bf[2];
                const float* p = sK + (nt*8 + r)*68 + ks*8 + c;
                bf[0] = __float_as_uint(p[0]);
                bf[1] = __float_as_uint(p[4]);
                mma8(s[nt], aq[ks], bf);
            }
        }
        // normalized probabilities -> smem P tile
        #pragma unroll
        for (int nt = 0; nt < 16; nt++){
            float p0 = exp2f(s[nt][0]*CF) * inv0;
            float p1 = exp2f(s[nt][1]*CF) * inv0;
            float p2 = exp2f(s[nt][2]*CF) * inv1;
            float p3 = exp2f(s[nt][3]*CF) * inv1;
            float* pp = sP + (warp*16 + r)*132 + nt*8 + 2*c;
            pp[0] = p0; pp[1] = p1;
            pp[8*132] = p2; pp[8*132 + 1] = p3;
        }
        __syncthreads();

        // coalesced att store (one warp per row, float4)
        #pragma unroll
        for (int i = 0; i < 16; i++){
            const int idx = t + 256*i, row = idx >> 5, c4 = (idx & 31) * 4;
            *(float4*)(attg + (size_t)row*TT + kb*128 + c4) = *(const float4*)(sP + row*132 + c4);
        }
        // Y += P * V
        #pragma unroll
        for (int ks = 0; ks < 16; ks++){
            uint32_t ap[4];
            const float* p = sP + (warp*16 + r)*132 + ks*8 + c;
            ap[0] = __float_as_uint(p[0]);
            ap[1] = __float_as_uint(p[8*132]);
            ap[2] = __float_as_uint(p[4]);
            ap[3] = __float_as_uint(p[8*132 + 4]);
            #pragma unroll
            for (int nt = 0; nt < 8; nt++){
                uint32_t bv[2];
                const float* q2 = sV + (ks*8 + c)*72 + nt*8 + r;
                bv[0] = __float_as_uint(q2[0]);
                bv[1] = __float_as_uint(q2[4*72]);
                mma8(yv[nt], ap, bv);
            }
        }
    }

    // write Y to g_y in [B,T,D] layout
    #pragma unroll
    for (int nt = 0; nt < 8; nt++){
        const int row = qb*128 + warp*16 + r;
        const int col = h*64 + nt*8 + 2*c;
        *(float2*)(g_y + ((size_t)b*TT + row)*DD + col)     = make_float2(yv[nt][0], yv[nt][1]);
        *(float2*)(g_y + ((size_t)b*TT + row + 8)*DD + col) = make_float2(yv[nt][2], yv[nt][3]);
    }
}

// ---------------------------------------------------------------------------
// K3: output projection + bias.  grid (32, 8), 256 thr.
// ---------------------------------------------------------------------------
extern "C" __global__ void __launch_bounds__(256, 1)
oproj_kernel(const float* __restrict__ Wo, const float* __restrict__ bo,
             float* __restrict__ out)
{
    __shared__ float sA[128*36];
    __shared__ float sB[128*36];
    const int m0 = blockIdx.x * 128, n0 = blockIdx.y * 128;

    float acc[16][4];
    gemm_128_128(g_y, Wo, m0, n0, acc, sA, sB);

    const int lane = threadIdx.x & 31, warp = threadIdx.x >> 5;
    const int wm = (warp >> 2) * 64, wn = (warp & 3) * 32;
    const int r = lane >> 2, c = lane & 3;
    #pragma unroll
    for (int mt = 0; mt < 4; mt++){
        #pragma unroll
        for (int nt = 0; nt < 4; nt++){
            const float* f = acc[mt*4 + nt];
            const int m_ = m0 + wm + mt*16 + r;
            const int n_ = n0 + wn + nt*8 + c*2;
            const float2 bias = *(const float2*)(bo + n_);
            float2 v0 = make_float2(f[0] + bias.x, f[1] + bias.y);
            float2 v1 = make_float2(f[2] + bias.x, f[3] + bias.y);
            *(float2*)(out + (size_t)m_*DD + n_)       = v0;
            *(float2*)(out + (size_t)(m_ + 8)*DD + n_) = v1;
        }
    }
}

// ---------------------------------------------------------------------------
extern "C" void kernel_launch(void* const* d_in, const int* in_sizes, int n_in,
                              void* d_out, int out_size)
{
    (void)in_sizes; (void)n_in; (void)out_size;
    const float* x  = (const float*)d_in[0];
    const float* Wq = (const float*)d_in[1];
    const float* Wk = (const float*)d_in[2];
    const float* Wv = (const float*)d_in[3];
    const float* Wo = (const float*)d_in[4];
    const float* bo = (const float*)d_in[5];

    float* y_out = (float*)d_out;                       // [B,T,D]
    float* att   = y_out + (size_t)BT * DD;             // [B,H,T,T]

    const int attn_smem = (128*68 + 128*68 + 128*72 + 128*132 + 128) * 4; // 174592 B
    cudaFuncSetAttribute(attn_kernel, cudaFuncAttributeMaxDynamicSharedMemorySize, attn_smem);

    qkv_kernel<<<dim3(32, 8, 3), 256>>>(x, Wq, Wk, Wv);
    attn_kernel<<<dim3(16, 16, 2), 256, attn_smem>>>(att);
    oproj_kernel<<<dim3(32, 8), 256>>>(Wo, bo, y_out);
}